// round 17
// baseline (speedup 1.0000x reference)
#include <cuda_runtime.h>
#include <cuda_fp16.h>
#include <cstdint>
#include <math.h>

// Shapes (fixed): B=32, T=2000, D=512, halves of 256, 3H=768.
#define M_TOTAL   64000
#define B_SZ      32
#define T_LEN     2000
#define D_FULL    512
#define D_HALF    256
#define D_HALF2   256            // D_FULL in half2 units
#define N_COLS    768

// Scan chunking (80 chunks of 25 -> 2560 blocks, near-full occupancy)
#define NCHUNK 80
#define CLEN   25

// GEMM tiling (mma.sync m16n8k16 fp16)
#define BM 128
#define BN 128
#define BK 16
#define NKT (D_HALF / BK)        // 16 k-tiles
#define NST (NKT / 2)            // 8 supertiles (BK=32 staging)
#define NMBLK (M_TOTAL / BM)     // 500
#define TILE_U32 1024            // 128 x 16 fp16 = 4KB
#define STILE_U32 (2 * TILE_U32) // supertile = 8KB

// Scratch (device globals: allocation-free per harness rules).
__device__ __half2 g_xt[M_TOTAL * D_HALF2];
__device__ __half2 g_f [M_TOTAL * D_HALF2];
__device__ __half2 g_r [M_TOTAL * D_HALF2];
__device__ float g_P  [B_SZ * NCHUNK * D_FULL];
__device__ float g_C  [B_SZ * NCHUNK * D_FULL];
__device__ float g_cin[B_SZ * NCHUNK * D_FULL];
// pre-converted fp16 operand images in fragment-packed SMEM tile layout
__device__ uint32_t g_xc[2 * NMBLK * NKT * TILE_U32];   // 65.5 MB
__device__ uint32_t g_wc[2 * 6 * NKT * TILE_U32];       // 0.8 MB

__device__ __forceinline__ float sigmoidf_(float v) {
    return 1.0f / (1.0f + __expf(-v));
}

__device__ __forceinline__ uint32_t smem_u32(const void* p) {
    uint32_t a;
    asm("{ .reg .u64 t; cvta.to.shared.u64 t, %1; cvt.u32.u64 %0, t; }"
        : "=r"(a) : "l"(p));
    return a;
}

__device__ __forceinline__ uint32_t pack_h2(float lo, float hi) {
    __half2 h = __halves2half2(__float2half_rn(lo), __float2half_rn(hi));
    return *(uint32_t*)&h;
}

__device__ __forceinline__ void cp_async16(uint32_t smem_dst, const void* gptr) {
    asm volatile("cp.async.ca.shared.global [%0], [%1], 16;"
                 :: "r"(smem_dst), "l"(gptr) : "memory");
}
__device__ __forceinline__ void cp_async_commit() {
    asm volatile("cp.async.commit_group;" ::: "memory");
}
template <int N>
__device__ __forceinline__ void cp_async_wait() {
    asm volatile("cp.async.wait_group %0;" :: "n"(N) : "memory");
}

__device__ __forceinline__ void mma_f16(float* c, uint32_t a0, uint32_t a1,
                                        uint32_t a2, uint32_t a3,
                                        uint32_t b0, uint32_t b1) {
    asm volatile(
        "mma.sync.aligned.m16n8k16.row.col.f32.f16.f16.f32 "
        "{%0,%1,%2,%3}, {%4,%5,%6,%7}, {%8,%9}, {%0,%1,%2,%3};"
        : "+f"(c[0]), "+f"(c[1]), "+f"(c[2]), "+f"(c[3])
        : "r"(a0), "r"(a1), "r"(a2), "r"(a3), "r"(b0), "r"(b1));
}

// Fragment-packed layouts (validated R8/R9/R14): NO row-dependent swizzle.
// uint32 at a_off(r,p) holds fp16 pair (channels 2p, 2p+1) of row r.
__device__ __forceinline__ int a_off(int r, int p) {
    return ((r >> 4) << 7) + ((r & 7) << 4) + ((p & 3) << 2)
         + (((r >> 3) & 1) << 1) + (p >> 2);
}
__device__ __forceinline__ int b_off(int n, int p) {
    return (n << 3) + ((p & 3) << 1) + (p >> 2);
}

// ---------------------------------------------------------------------------
// Fused pre-pass: y<500 converts x tiles; y>=500 converts W tiles (nblk=y-500).
// ---------------------------------------------------------------------------
__global__ __launch_bounds__(256)
void convert_kernel(const float* __restrict__ x,
                    const float* __restrict__ W1, const float* __restrict__ W2)
{
    const int kt  = blockIdx.x;
    const int s   = blockIdx.z;
    const int tid = threadIdx.x;

    if (blockIdx.y < NMBLK) {
        const int mblk = blockIdx.y;
        uint32_t* dst = g_xc + ((size_t)((s * NMBLK + mblk) * NKT + kt)) * TILE_U32;
        const float* src = x + (size_t)(mblk * BM) * D_FULL + s * D_HALF + kt * BK;
        #pragma unroll
        for (int j = 0; j < 2; j++) {
            const int idx = tid + 256 * j;        // 0..511
            const int row = idx >> 2;
            const int c4  = idx & 3;
            float4 v = *(const float4*)(src + (size_t)row * D_FULL + 4 * c4);
            dst[a_off(row, 2 * c4)]     = pack_h2(v.x, v.y);
            dst[a_off(row, 2 * c4 + 1)] = pack_h2(v.z, v.w);
        }
    } else {
        const int nblk = blockIdx.y - NMBLK;      // 0..5
        const float* W = s ? W2 : W1;
        uint32_t* dst = g_wc + ((size_t)((s * 6 + nblk) * NKT + kt)) * TILE_U32;
        const float* src = W + (size_t)(kt * BK) * N_COLS + nblk * BN;
        #pragma unroll
        for (int j = 0; j < 4; j++) {
            const int idx = tid + 256 * j;        // p*128 + n
            const int p = idx >> 7;
            const int n = idx & 127;
            const float w0 = src[(size_t)(2 * p)     * N_COLS + n];
            const float w1 = src[(size_t)(2 * p + 1) * N_COLS + n];
            dst[b_off(n, p)] = pack_h2(w0, w1);
        }
    }
}

// ---------------------------------------------------------------------------
// Kernel 1: fp16 mma.sync (m16n8k16) GEMM.
// 3-stage supertile cp.async pipeline (48KB static smem, known-good R10-R14).
// ---------------------------------------------------------------------------
__global__ __launch_bounds__(256, 2)
void gemm_mma_kernel(const float* __restrict__ bf1, const float* __restrict__ br1,
                     const float* __restrict__ bf2, const float* __restrict__ br2)
{
    const int s    = blockIdx.x / 6;
    const int nblk = blockIdx.x % 6;
    const int mblk = blockIdx.y;

    const float* bf = s ? bf2 : bf1;
    const float* br = s ? br2 : br1;

    __shared__ uint32_t sA[3][STILE_U32];  // 3 x 8KB
    __shared__ uint32_t sB[3][STILE_U32];  // 3 x 8KB

    const int tid    = threadIdx.x;
    const int wid    = tid >> 5;
    const int lid    = tid & 31;
    const int gid    = lid >> 2;
    const int tig    = lid & 3;
    const int warp_m = wid >> 2;
    const int warp_n = wid & 3;

    const uint32_t* Asrc = g_xc + ((size_t)(s * NMBLK + mblk)) * NKT * TILE_U32;
    const uint32_t* Bsrc = g_wc + ((size_t)(s * 6 + nblk)) * NKT * TILE_U32;

    auto prefetch = [&](int st) {
        const int buf = st % 3;
        const int e0 = tid * 4;
        const int e1 = tid * 4 + TILE_U32;
        const uint32_t* ga = Asrc + (size_t)st * STILE_U32;
        const uint32_t* gb = Bsrc + (size_t)st * STILE_U32;
        cp_async16(smem_u32(&sA[buf][e0]), ga + e0);
        cp_async16(smem_u32(&sA[buf][e1]), ga + e1);
        cp_async16(smem_u32(&sB[buf][e0]), gb + e0);
        cp_async16(smem_u32(&sB[buf][e1]), gb + e1);
        cp_async_commit();
    };

    float acc[4][4][4];
    #pragma unroll
    for (int mi = 0; mi < 4; mi++)
        #pragma unroll
        for (int ni = 0; ni < 4; ni++)
            #pragma unroll
            for (int q = 0; q < 4; q++) acc[mi][ni][q] = 0.0f;

    prefetch(0);
    prefetch(1);

    #pragma unroll 1
    for (int st = 0; st < NST; st++) {
        // tail (R6 lesson): on the final iteration the newest committed group
        // is supertile NST-1 itself — drain fully.
        if (st + 1 < NST) cp_async_wait<1>();
        else              cp_async_wait<0>();
        __syncthreads();   // tile st resident; all threads done with st-1
        if (st + 2 < NST) prefetch(st + 2);   // refills buf (st-1)%3: safe

        #pragma unroll
        for (int sub = 0; sub < 2; sub++) {
            const uint32_t* A  = &sA[st % 3][sub * TILE_U32];
            const uint32_t* Bs = &sB[st % 3][sub * TILE_U32];

            uint4 afr[4];
            #pragma unroll
            for (int mi = 0; mi < 4; mi++)
                afr[mi] = *(const uint4*)&A[(warp_m * 4 + mi) * 128 + gid * 16 + tig * 4];

            #pragma unroll
            for (int ni = 0; ni < 4; ni++) {
                const int n = warp_n * 32 + ni * 8 + gid;
                const uint2 bv = *(const uint2*)&Bs[n * 8 + tig * 2];
                #pragma unroll
                for (int mi = 0; mi < 4; mi++)
                    mma_f16(acc[mi][ni], afr[mi].x, afr[mi].z, afr[mi].y, afr[mi].w,
                            bv.x, bv.y);
            }
        }
    }

    // ---- epilogue: fused bias + sigmoid, half2 stores ----
    const int n0      = nblk * BN;
    const int region  = n0 >> 8;
    __half2* dst      = (region == 0) ? g_xt : ((region == 1) ? g_f : g_r);
    const float* bias = (region == 1) ? bf : br;

    #pragma unroll
    for (int mi = 0; mi < 4; mi++) {
        const int row0 = mblk * BM + warp_m * 64 + mi * 16 + gid;
        #pragma unroll
        for (int ni = 0; ni < 4; ni++) {
            const int h = (n0 & (D_HALF - 1)) + warp_n * 32 + ni * 8 + 2 * tig;
            float v0 = acc[mi][ni][0], v1 = acc[mi][ni][1];
            float v2 = acc[mi][ni][2], v3 = acc[mi][ni][3];
            if (region != 0) {
                const float b0 = __ldg(bias + h), b1 = __ldg(bias + h + 1);
                v0 = sigmoidf_(v0 + b0);
                v1 = sigmoidf_(v1 + b1);
                v2 = sigmoidf_(v2 + b0);
                v3 = sigmoidf_(v3 + b1);
            }
            const size_t cp = (size_t)(s * D_HALF + h) >> 1;
            dst[(size_t)row0 * D_HALF2 + cp]       = __floats2half2_rn(v0, v1);
            dst[(size_t)(row0 + 8) * D_HALF2 + cp] = __floats2half2_rn(v2, v3);
        }
    }
}

// ---------------------------------------------------------------------------
// Scan phase 1: 128 threads, 4 channels/thread (2x half2); float4 summaries.
// Grid (1, NCHUNK, B_SZ) = 2560 blocks.
// ---------------------------------------------------------------------------
__global__ __launch_bounds__(128)
void scan_phase1(void)
{
    const int c4    = threadIdx.x;        // 0..127 (channel quad)
    const int chunk = blockIdx.y;
    const int b     = blockIdx.z;

    const size_t base = ((size_t)b * T_LEN + (size_t)chunk * CLEN) * D_HALF2 + 2 * c4;
    const __half2* pf  = g_f  + base;
    const __half2* pxt = g_xt + base;

    float4 P = make_float4(1.0f, 1.0f, 1.0f, 1.0f);
    float4 C = make_float4(0.0f, 0.0f, 0.0f, 0.0f);
    #pragma unroll 5
    for (int t = 0; t < CLEN; t++) {
        const size_t off = (size_t)t * D_HALF2;
        const float2 f0 = __half22float2(pf[off]),  f1 = __half22float2(pf[off + 1]);
        const float2 x0 = __half22float2(pxt[off]), x1 = __half22float2(pxt[off + 1]);
        C.x = fmaf(f0.x, C.x, (1.0f - f0.x) * x0.x);
        C.y = fmaf(f0.y, C.y, (1.0f - f0.y) * x0.y);
        C.z = fmaf(f1.x, C.z, (1.0f - f1.x) * x1.x);
        C.w = fmaf(f1.y, C.w, (1.0f - f1.y) * x1.y);
        P.x *= f0.x;  P.y *= f0.y;  P.z *= f1.x;  P.w *= f1.y;
    }
    const size_t sidx = ((size_t)b * NCHUNK + chunk) * D_FULL + 4 * c4;
    *(float4*)&g_P[sidx] = P;
    *(float4*)&g_C[sidx] = C;
}

// ---------------------------------------------------------------------------
// Scan phase 2: serial scan over chunk summaries -> carry-in per chunk.
// 4096 threads, 4 channels/thread (float4).
// ---------------------------------------------------------------------------
__global__ __launch_bounds__(256)
void scan_phase2(void)
{
    const int idx = blockIdx.x * 256 + threadIdx.x;   // 0..4095 (channel quads)
    const int b  = idx >> 7;                          // / 128 quads per batch
    const int c4 = idx & 127;

    float4 carry = make_float4(0.0f, 0.0f, 0.0f, 0.0f);
    #pragma unroll 4
    for (int k = 0; k < NCHUNK; k++) {
        const size_t sidx = ((size_t)b * NCHUNK + k) * D_FULL + 4 * c4;
        *(float4*)&g_cin[sidx] = carry;
        const float4 Pv = *(const float4*)&g_P[sidx];
        const float4 Cv = *(const float4*)&g_C[sidx];
        carry.x = fmaf(Pv.x, carry.x, Cv.x);
        carry.y = fmaf(Pv.y, carry.y, Cv.y);
        carry.z = fmaf(Pv.z, carry.z, Cv.z);
        carry.w = fmaf(Pv.w, carry.w, Cv.w);
    }
}

// ---------------------------------------------------------------------------
// Scan phase 3: carry-in from g_cin; recurrence + highway. x read from the
// fp16 image g_xc (plain a_off layout — no swizzle; R13 lesson).
// 128 threads, 4 channels/thread. Grid (1, NCHUNK, B_SZ) = 2560 blocks.
// ---------------------------------------------------------------------------
__global__ __launch_bounds__(128)
void scan_phase3(float* __restrict__ out)
{
    const int c4    = threadIdx.x;        // 0..127
    const int chunk = blockIdx.y;
    const int b     = blockIdx.z;

    float4 cacc = *(const float4*)&g_cin[((size_t)b * NCHUNK + chunk) * D_FULL + 4 * c4];

    const size_t base = ((size_t)b * T_LEN + (size_t)chunk * CLEN) * D_HALF2 + 2 * c4;
    const __half2* pf  = g_f  + base;
    const __half2* pxt = g_xt + base;
    const __half2* pr  = g_r  + base;
    float*         po  = out + 2 * base;

    // ---- x image addressing: channels c..c+3, c = 4*c4 ----
    const int c   = 4 * c4;
    const int s   = c >> 8;                 // half
    const int kt  = (c >> 4) & 15;          // k-tile within half
    const int p0  = (c & 15) >> 1;          // even pair index {0,2,4,6}
    const int koff0 = 4 * (p0 & 3) + (p0 >> 2);
    const int koff1 = koff0 + 4;            // pair p0+1
    const uint32_t* img_half = g_xc + (size_t)s * NMBLK * NKT * TILE_U32
                                    + (size_t)kt * TILE_U32;
    const int m0 = b * T_LEN + chunk * CLEN;

    #pragma unroll 5
    for (int t = 0; t < CLEN; t++) {
        const size_t off = (size_t)t * D_HALF2;
        const float2 f0 = __half22float2(pf[off]),  f1 = __half22float2(pf[off + 1]);
        const float2 t0 = __half22float2(pxt[off]), t1 = __half22float2(pxt[off + 1]);
        const float2 r0 = __half22float2(pr[off]),  r1 = __half22float2(pr[off + 1]);

        // x from fp16 image: row m -> tile m>>7, in-tile row rr = m&127
        const int m  = m0 + t;
        const int rr = m & 127;
        const uint32_t* tb = img_half + (size_t)(m >> 7) * (NKT * TILE_U32);
        const int rbase = ((rr >> 4) << 7) + ((rr & 7) << 4) + (((rr >> 3) & 1) << 1);
        const uint32_t w0 = tb[rbase + koff0];          // ch c, c+1
        const uint32_t w1 = tb[rbase + koff1];          // ch c+2, c+3
        const float2 xv0 = __half22float2(*(const __half2*)&w0);
        const float2 xv1 = __half22float2(*(const __half2*)&w1);

        cacc.x = fmaf(f0.x, cacc.x, (1.0f - f0.x) * t0.x);
        cacc.y = fmaf(f0.y, cacc.y, (1.0f - f0.y) * t0.y);
        cacc.z = fmaf(f1.x, cacc.z, (1.0f - f1.x) * t1.x);
        cacc.w = fmaf(f1.y, cacc.w, (1.0f - f1.y) * t1.y);
        float4 h;
        h.x = fmaf(r0.x, cacc.x, (1.0f - r0.x) * xv0.x);
        h.y = fmaf(r0.y, cacc.y, (1.0f - r0.y) * xv0.y);
        h.z = fmaf(r1.x, cacc.z, (1.0f - r1.x) * xv1.x);
        h.w = fmaf(r1.y, cacc.w, (1.0f - r1.y) * xv1.y);
        *(float4*)(po + 2 * off) = h;
    }
}

// ---------------------------------------------------------------------------
extern "C" void kernel_launch(void* const* d_in, const int* in_sizes, int n_in,
                              void* d_out, int out_size)
{
    const float* x   = (const float*)d_in[0];
    const float* W1  = (const float*)d_in[1];
    const float* bf1 = (const float*)d_in[2];
    const float* br1 = (const float*)d_in[3];
    const float* W2  = (const float*)d_in[4];
    const float* bf2 = (const float*)d_in[5];
    const float* br2 = (const float*)d_in[6];
    float* out = (float*)d_out;

    (void)n_in; (void)in_sizes; (void)out_size;

    dim3 cgrid(NKT, NMBLK + 6, 2);             // (16, 506, 2) fused convert
    convert_kernel<<<cgrid, 256>>>(x, W1, W2);

    dim3 ggrid(12, NMBLK);                     // (12, 500)
    gemm_mma_kernel<<<ggrid, 256>>>(bf1, br1, bf2, br2);

    dim3 sgrid(1, NCHUNK, B_SZ);               // (1, 80, 32) = 2560 blocks
    scan_phase1<<<sgrid, 128>>>();
    scan_phase2<<<(B_SZ * D_FULL / 4) / 256, 256>>>();   // 16 blocks
    scan_phase3<<<sgrid, 128>>>(out);
}